// round 5
// baseline (speedup 1.0000x reference)
#include <cuda_runtime.h>
#include <cuda_fp16.h>
#include <math.h>
#include <stdint.h>

// ---------------- problem constants ----------------
#define NB    1000      // B
#define NN    20        // neighbors per node
#define D_    172
#define DT_   100
#define E_    272       // D + DT
#define DK_   444       // D + DT + DE
#define KPAD  448       // padded K for the fp16 GEMM A buffer
#define HD    136       // head dim (E/2)

#define R1    (NB*NN)    // 20000 layer-1 queries
#define ROWS1 (R1*NN)    // 400000 layer-1 kv rows

// ---------------- scratch (device globals; no allocs allowed) ----------------
__device__ __align__(16) __half g_Ah [(size_t)ROWS1 * KPAD];  // fp16 gathered GEMM input
__device__ __align__(16) __half g_Wh [(size_t)4 * E_ * KPAD]; // fp16 weights [l*2+mat][272][448]
__device__ float g_A32 [(size_t)R1 * KPAD];   // fp32 input for MLP gemm
__device__ float g_K   [(size_t)ROWS1 * E_];
__device__ float g_V   [(size_t)ROWS1 * E_];
__device__ float g_SRC [(size_t)R1 * D_];
__device__ float g_Q   [(size_t)R1 * E_];
__device__ float g_CTX [(size_t)R1 * E_];
__device__ float g_O   [(size_t)R1 * E_];
__device__ float g_H   [(size_t)R1 * D_];
__device__ float g_EMB [(size_t)R1 * D_];
__device__ float g_CQ  [2 * E_];
__device__ int   g_AM  [R1];

// ============================================================================
// fp16 tensor-core GEMM via mma.sync (HMMA, valid at compute_103):
//   C[M, 272] = A[M, 448]fp16 @ W[272, 448]fp16^T + bias   (fp32 accum/output)
// CTA tile 128x96, BK=32 halfs, cp.async double buffer, ldmatrix fragments.
// Grid: (3, ceil(M/128)), 256 threads (8 warps as 4m x 2n, warp tile 32x48).
// ============================================================================
#define AST 40   // smem A row stride (halfs), padded
#define BST 40   // smem B row stride (halfs), padded

__device__ __forceinline__ void ldsm_x4(uint32_t* r, uint32_t addr) {
    asm volatile("ldmatrix.sync.aligned.m8n8.x4.shared.b16 {%0,%1,%2,%3}, [%4];"
                 : "=r"(r[0]), "=r"(r[1]), "=r"(r[2]), "=r"(r[3]) : "r"(addr));
}
__device__ __forceinline__ void mma16816(float* d, const uint32_t* a, uint32_t b0, uint32_t b1) {
    asm volatile("mma.sync.aligned.m16n8k16.row.col.f32.f16.f16.f32 "
                 "{%0,%1,%2,%3}, {%4,%5,%6,%7}, {%8,%9}, {%0,%1,%2,%3};"
                 : "+f"(d[0]), "+f"(d[1]), "+f"(d[2]), "+f"(d[3])
                 : "r"(a[0]), "r"(a[1]), "r"(a[2]), "r"(a[3]), "r"(b0), "r"(b1));
}
__device__ __forceinline__ void cp16(uint32_t dst, const void* src, int sz) {
    asm volatile("cp.async.cg.shared.global [%0], [%1], 16, %2;"
                 :: "r"(dst), "l"(src), "r"(sz));
}

__global__ __launch_bounds__(256)
void hgemm_mma(const __half* __restrict__ A, const __half* __restrict__ W,
               const float* __restrict__ bias, float* __restrict__ C, int M)
{
    __shared__ __half sA[2][128 * AST];
    __shared__ __half sB[2][96 * BST];

    const int tid  = threadIdx.x;
    const int lane = tid & 31, wid = tid >> 5;
    const int warp_m = wid & 3, warp_n = wid >> 2;
    const int m0 = blockIdx.y * 128;
    const int n0 = blockIdx.x * 96;

    float acc[2][6][4];
    #pragma unroll
    for (int i = 0; i < 2; i++)
        #pragma unroll
        for (int j = 0; j < 6; j++)
            #pragma unroll
            for (int q = 0; q < 4; q++) acc[i][j][q] = 0.f;

    // ---- async tile loaders (zero-fill OOB rows) ----
    auto loadA = [&](int s, int k0) {
        #pragma unroll
        for (int c = tid; c < 512; c += 256) {
            int row = c >> 2, seg = c & 3;
            int gm = m0 + row;
            uint32_t dst = (uint32_t)__cvta_generic_to_shared(&sA[s][row * AST + seg * 8]);
            cp16(dst, A + (size_t)gm * KPAD + k0 + seg * 8, gm < M ? 16 : 0);
        }
    };
    auto loadB = [&](int s, int k0) {
        #pragma unroll
        for (int c = tid; c < 384; c += 256) {
            int row = c >> 2, seg = c & 3;
            int gn = n0 + row;
            uint32_t dst = (uint32_t)__cvta_generic_to_shared(&sB[s][row * BST + seg * 8]);
            cp16(dst, W + (size_t)gn * KPAD + k0 + seg * 8, gn < E_ ? 16 : 0);
        }
    };

    auto computeStage = [&](int s) {
        #pragma unroll
        for (int kk = 0; kk < 2; ++kk) {
            uint32_t afr[2][4];
            #pragma unroll
            for (int i = 0; i < 2; ++i) {
                uint32_t addr = (uint32_t)__cvta_generic_to_shared(
                    &sA[s][(warp_m * 32 + i * 16 + (lane & 15)) * AST + kk * 16 + (lane >> 4) * 8]);
                ldsm_x4(afr[i], addr);
            }
            uint32_t bfr[3][4];
            #pragma unroll
            for (int j = 0; j < 3; ++j) {
                int nrow = warp_n * 48 + j * 16 + ((lane >> 4) << 3) + (lane & 7);
                int kcol = kk * 16 + ((lane >> 3) & 1) * 8;
                uint32_t addr = (uint32_t)__cvta_generic_to_shared(&sB[s][nrow * BST + kcol]);
                ldsm_x4(bfr[j], addr);
            }
            #pragma unroll
            for (int i = 0; i < 2; ++i)
                #pragma unroll
                for (int j = 0; j < 6; ++j)
                    mma16816(acc[i][j], afr[i], bfr[j >> 1][(j & 1) * 2], bfr[j >> 1][(j & 1) * 2 + 1]);
        }
    };

    loadA(0, 0); loadB(0, 0);
    asm volatile("cp.async.commit_group;" ::: "memory");

    for (int c = 0; c < 14; ++c) {
        if (c + 1 < 14) {
            loadA((c + 1) & 1, (c + 1) * 32);
            loadB((c + 1) & 1, (c + 1) * 32);
            asm volatile("cp.async.commit_group;" ::: "memory");
            asm volatile("cp.async.wait_group 1;" ::: "memory");
        } else {
            asm volatile("cp.async.wait_group 0;" ::: "memory");
        }
        __syncthreads();
        computeStage(c & 1);
        __syncthreads();
    }

    // ---- epilogue ----
    #pragma unroll
    for (int i = 0; i < 2; ++i) {
        int row = m0 + warp_m * 32 + i * 16 + (lane >> 2);
        #pragma unroll
        for (int j = 0; j < 6; ++j) {
            int col = n0 + warp_n * 48 + j * 8 + (lane & 3) * 2;
            if (col < E_) {
                float b0 = bias[col], b1 = bias[col + 1];
                if (row < M) {
                    C[(size_t)row * E_ + col]     = acc[i][j][0] + b0;
                    C[(size_t)row * E_ + col + 1] = acc[i][j][1] + b1;
                }
                if (row + 8 < M) {
                    C[(size_t)(row + 8) * E_ + col]     = acc[i][j][2] + b0;
                    C[(size_t)(row + 8) * E_ + col + 1] = acc[i][j][3] + b1;
                }
            }
        }
    }
}

// ---------------- weight conversion: Wk/Wv (2 layers) -> fp16 padded [4][272][448] ----------
__global__ void convert_w(const float* __restrict__ Wk, const float* __restrict__ Wv)
{
    const long total = 4L * E_ * KPAD;
    for (long i = (long)blockIdx.x * blockDim.x + threadIdx.x; i < total;
         i += (long)gridDim.x * blockDim.x) {
        int k = (int)(i % KPAD);
        long r = i / KPAD;
        int n = (int)(r % E_);
        int lm = (int)(r / E_);
        int mat = lm & 1, l = lm >> 1;
        const float* W = mat ? Wv : Wk;
        float v = (k < DK_) ? W[((size_t)l * E_ + n) * DK_ + k] : 0.f;
        g_Wh[i] = __float2half(v);
    }
}

// ---------------- constant part of q: c_q[l] = cos(b_time) @ Wq[l][:,172:].T + bq[l] ----
__global__ void cq_kernel(const float* __restrict__ Wq, const float* __restrict__ bq,
                          const float* __restrict__ b_time)
{
    int l = blockIdx.x;
    int n = threadIdx.x;
    if (n < E_) {
        float s = bq[l*E_ + n];
        const float* w = Wq + (size_t)l*E_*E_ + (size_t)n*E_ + D_;
        #pragma unroll 4
        for (int j = 0; j < DT_; j++) s += cosf(b_time[j]) * w[j];
        g_CQ[l*E_ + n] = s;
    }
}

// ---------------- generic row gather ----------------
__global__ void gather_rows(const float* __restrict__ src, const int* __restrict__ idx,
                            float* __restrict__ dst, int rows, int width)
{
    long total = (long)rows * width;
    for (long i = (long)blockIdx.x*blockDim.x + threadIdx.x; i < total;
         i += (long)gridDim.x * blockDim.x) {
        int r = (int)(i / width);
        int k = (int)(i % width);
        dst[i] = src[(size_t)idx[r]*width + k];
    }
}

// ---------------- build fp16 KV GEMM rows: [neigh(172) | cos(dt*w+b)(100) | edge(172) | 0] ----
__global__ void build_kv(const float* __restrict__ neigh_base, int gather_flag,
                         const int* __restrict__ neighbors,
                         const float* __restrict__ edge_features,
                         const int* __restrict__ edge_idxs,
                         const float* __restrict__ edge_times,
                         const float* __restrict__ timestamps, int ts_div,
                         const float* __restrict__ w_time, const float* __restrict__ b_time,
                         int rows)
{
    int m = blockIdx.x;
    if (m >= rows) return;
    __half2* out = (__half2*)(g_Ah + (size_t)m * KPAD);
    const float* nb = gather_flag ? (neigh_base + (size_t)neighbors[m]*D_)
                                  : (neigh_base + (size_t)m*D_);
    float dt = timestamps[m / ts_div] - edge_times[m];
    const float* ef = edge_features + (size_t)edge_idxs[m]*D_;
    for (int i = threadIdx.x; i < KPAD/2; i += blockDim.x) {
        int k = i * 2;
        float a, b;
        if (k < D_)            { a = nb[k]; b = nb[k+1]; }
        else if (k < E_)       { int j = k - D_;
                                 a = cosf(dt*w_time[j]   + b_time[j]);
                                 b = cosf(dt*w_time[j+1] + b_time[j+1]); }
        else if (k < DK_)      { a = ef[k - E_]; b = ef[k - E_ + 1]; }
        else                   { a = 0.f; b = 0.f; }
        out[i] = __floats2half2_rn(a, b);
    }
}

// ---------------- build fp32 MLP input rows: [o(272) | src(172) | 0pad] ----------------
__global__ void build_cat(const float* __restrict__ O, const float* __restrict__ S, int rows)
{
    long total = (long)rows * KPAD;
    for (long i = (long)blockIdx.x*blockDim.x + threadIdx.x; i < total;
         i += (long)gridDim.x * blockDim.x) {
        int r = (int)(i / KPAD);
        int k = (int)(i % KPAD);
        float v;
        if      (k < E_)  v = O[(size_t)r*E_ + k];
        else if (k < DK_) v = S[(size_t)r*D_ + (k - E_)];
        else              v = 0.f;
        g_A32[i] = v;
    }
}

// ---------------- fp32 tiled GEMM (small GEMMs): C = A @ W^T + bias ----------------
#define BM 128
#define BN 128
#define BK 16

__global__ __launch_bounds__(256)
void gemm_bias(const float* __restrict__ A, int lda,
               const float* __restrict__ W, int ldw,
               const float* __restrict__ bias,
               const int*   __restrict__ rowzero,
               float* __restrict__ C, int ldc,
               int M, int Ncols, int K, int relu)
{
    __shared__ float As[BK][BM + 4];
    __shared__ float Bs[BK][BN + 4];

    int tid = threadIdx.x;
    int tx = tid & 15, ty = tid >> 4;
    int m0 = blockIdx.y * BM, n0 = blockIdx.x * BN;

    float acc[8][8];
    #pragma unroll
    for (int i = 0; i < 8; i++)
        #pragma unroll
        for (int j = 0; j < 8; j++) acc[i][j] = 0.f;

    for (int k0 = 0; k0 < K; k0 += BK) {
        #pragma unroll
        for (int jj = 0; jj < 2; jj++) {
            int v  = tid + 256*jj;
            int m  = v >> 2;
            int k4 = v & 3;
            int gk = k0 + k4*4;

            float4 av = make_float4(0.f,0.f,0.f,0.f);
            int gm = m0 + m;
            if (gm < M && gk < K)
                av = *(const float4*)(A + (size_t)gm*lda + gk);
            As[k4*4+0][m]=av.x; As[k4*4+1][m]=av.y; As[k4*4+2][m]=av.z; As[k4*4+3][m]=av.w;

            float4 bv = make_float4(0.f,0.f,0.f,0.f);
            int gn = n0 + m;
            if (gn < Ncols && gk < K)
                bv = *(const float4*)(W + (size_t)gn*ldw + gk);
            Bs[k4*4+0][m]=bv.x; Bs[k4*4+1][m]=bv.y; Bs[k4*4+2][m]=bv.z; Bs[k4*4+3][m]=bv.w;
        }
        __syncthreads();

        #pragma unroll
        for (int kk = 0; kk < BK; kk++) {
            float ra[8], rb[8];
            #pragma unroll
            for (int i = 0; i < 8; i++) ra[i] = As[kk][ty + i*16];
            #pragma unroll
            for (int j = 0; j < 8; j++) rb[j] = Bs[kk][tx + j*16];
            #pragma unroll
            for (int i = 0; i < 8; i++)
                #pragma unroll
                for (int j = 0; j < 8; j++)
                    acc[i][j] += ra[i]*rb[j];
        }
        __syncthreads();
    }

    #pragma unroll
    for (int i = 0; i < 8; i++) {
        int gm = m0 + ty + i*16;
        if (gm >= M) continue;
        int rz = rowzero ? rowzero[gm] : 0;
        #pragma unroll
        for (int j = 0; j < 8; j++) {
            int gn = n0 + tx + j*16;
            if (gn >= Ncols) continue;
            float v = rz ? 0.f : (acc[i][j] + bias[gn]);
            if (relu) v = fmaxf(v, 0.f);
            C[(size_t)gm*ldc + gn] = v;
        }
    }
}

// ---------------- attention: warp per query row ----------------
__global__ void attn_kernel(const float* __restrict__ Q, const float* __restrict__ Kmat,
                            const float* __restrict__ Vmat, const int* __restrict__ nbrs,
                            float* __restrict__ CTX, int* __restrict__ AM, int R)
{
    __shared__ float qsh[4][E_];
    int warp = threadIdx.x >> 5, lane = threadIdx.x & 31;
    int row = blockIdx.x*4 + warp;
    if (row >= R) return;

    for (int d = lane; d < E_; d += 32) qsh[warp][d] = Q[(size_t)row*E_ + d];
    __syncwarp();

    const float scale = rsqrtf((float)HD);
    float a[2][NN];

    #pragma unroll
    for (int h = 0; h < 2; h++) {
        const float* qh = qsh[warp] + h*HD;
        for (int n = 0; n < NN; n++) {
            const float* kr = Kmat + ((size_t)row*NN + n)*E_ + h*HD;
            float s = 0.f;
            for (int d = lane; d < HD; d += 32) s += qh[d]*kr[d];
            #pragma unroll
            for (int o = 16; o; o >>= 1) s += __shfl_xor_sync(0xffffffffu, s, o);
            a[h][n] = s * scale;
        }
    }

    int allm = 1;
    #pragma unroll
    for (int n = 0; n < NN; n++) {
        int nb = nbrs[(size_t)row*NN + n];
        if (nb == 0) { a[0][n] = -1e9f; a[1][n] = -1e9f; }
        else allm = 0;
    }

    #pragma unroll
    for (int h = 0; h < 2; h++) {
        float mx = -3.4e38f;
        #pragma unroll
        for (int n = 0; n < NN; n++) mx = fmaxf(mx, a[h][n]);
        float ssum = 0.f;
        #pragma unroll
        for (int n = 0; n < NN; n++) { float e = expf(a[h][n] - mx); a[h][n] = e; ssum += e; }
        float inv = 1.f / ssum;
        #pragma unroll
        for (int n = 0; n < NN; n++) a[h][n] *= inv;
    }
    if (lane == 0) AM[row] = allm;

    for (int d = lane; d < E_; d += 32) {
        int h = d >= HD;
        float acc = 0.f;
        #pragma unroll
        for (int n = 0; n < NN; n++)
            acc += a[h][n] * Vmat[((size_t)row*NN + n)*E_ + d];
        CTX[(size_t)row*E_ + d] = acc;
    }
}

// ---------------- host side ----------------
static void launch_gemm(const float* A, int lda, const float* W, int ldw,
                        const float* bias, const int* rz,
                        float* C, int ldc, int M, int N, int K, int relu)
{
    dim3 grid((N + BN - 1)/BN, (M + BM - 1)/BM);
    gemm_bias<<<grid, 256>>>(A, lda, W, ldw, bias, rz, C, ldc, M, N, K, relu);
}

static void launch_hgemm(const __half* A, const __half* Wh, const float* bias, float* C, int M)
{
    dim3 grid(3, (M + 127)/128);
    hgemm_mma<<<grid, 256>>>(A, Wh, bias, C, M);
}

extern "C" void kernel_launch(void* const* d_in, const int* in_sizes, int n_in,
                              void* d_out, int out_size)
{
    const float* memory = (const float*)d_in[0];
    const float* edgef  = (const float*)d_in[1];
    const int*   srcn   = (const int*)  d_in[2];
    const float* ts     = (const float*)d_in[3];
    const int*   nb1    = (const int*)  d_in[4];
    const int*   ei1    = (const int*)  d_in[5];
    const float* et1    = (const float*)d_in[6];
    const int*   nb2    = (const int*)  d_in[7];
    const int*   ei2    = (const int*)  d_in[8];
    const float* et2    = (const float*)d_in[9];
    const float* w_time = (const float*)d_in[10];
    const float* b_time = (const float*)d_in[11];
    const float* Wq = (const float*)d_in[12];
    const float* bq = (const float*)d_in[13];
    const float* Wk = (const float*)d_in[14];
    const float* bk = (const float*)d_in[15];
    const float* Wv = (const float*)d_in[16];
    const float* bv = (const float*)d_in[17];
    const float* Wo = (const float*)d_in[18];
    const float* bo = (const float*)d_in[19];
    const float* W1 = (const float*)d_in[20];
    const float* b1 = (const float*)d_in[21];
    const float* W2 = (const float*)d_in[22];
    const float* b2 = (const float*)d_in[23];
    float* out = (float*)d_out;

    float *pA32, *pK, *pV, *pSRC, *pQ, *pCTX, *pO, *pH, *pEMB, *pCQ;
    __half *pAh, *pWh;
    int* pAM;
    cudaGetSymbolAddress((void**)&pAh,  g_Ah);
    cudaGetSymbolAddress((void**)&pWh,  g_Wh);
    cudaGetSymbolAddress((void**)&pA32, g_A32);
    cudaGetSymbolAddress((void**)&pK,   g_K);
    cudaGetSymbolAddress((void**)&pV,   g_V);
    cudaGetSymbolAddress((void**)&pSRC, g_SRC);
    cudaGetSymbolAddress((void**)&pQ,   g_Q);
    cudaGetSymbolAddress((void**)&pCTX, g_CTX);
    cudaGetSymbolAddress((void**)&pO,   g_O);
    cudaGetSymbolAddress((void**)&pH,   g_H);
    cudaGetSymbolAddress((void**)&pEMB, g_EMB);
    cudaGetSymbolAddress((void**)&pCQ,  g_CQ);
    cudaGetSymbolAddress((void**)&pAM,  g_AM);

    const size_t WSTRIDE = (size_t)E_ * KPAD;

    // weight fp16 conversion + constant query-time term
    convert_w<<<512, 256>>>(Wk, Wv);
    cq_kernel<<<2, E_>>>(Wq, bq, b_time);

    // ================= Layer 1 (l=0): 20000 queries x 20 neighbors =================
    {
        long tot = (long)R1 * D_;
        gather_rows<<<(int)((tot + 255)/256), 256>>>(memory, nb1, pSRC, R1, D_);
    }
    launch_gemm(pSRC, D_, Wq, E_, pCQ, nullptr, pQ, E_, R1, E_, D_, 0);

    build_kv<<<ROWS1, 128>>>(memory, 1, nb2, edgef, ei2, et2, ts, NN*NN, w_time, b_time, ROWS1);
    launch_hgemm(pAh, pWh + 0*WSTRIDE, bk, pK, ROWS1);
    launch_hgemm(pAh, pWh + 1*WSTRIDE, bv, pV, ROWS1);

    attn_kernel<<<(R1 + 3)/4, 128>>>(pQ, pK, pV, nb2, pCTX, pAM, R1);

    launch_gemm(pCTX, E_, Wo, E_, bo, pAM, pO, E_, R1, E_, E_, 0);
    {
        long tot = (long)R1 * KPAD;
        build_cat<<<(int)((tot + 255)/256), 256>>>(pO, pSRC, R1);
    }
    launch_gemm(pA32, KPAD, W1, DK_, b1, nullptr, pH, D_, R1, D_, DK_, 1);
    launch_gemm(pH, D_, W2, D_, b2, nullptr, pEMB, D_, R1, D_, D_, 0);

    // ================= Layer 2 (l=1): 1000 queries x 20 neighbors =================
    {
        long tot = (long)NB * D_;
        gather_rows<<<(int)((tot + 255)/256), 256>>>(memory, srcn, pSRC, NB, D_);
    }
    launch_gemm(pSRC, D_, Wq + (size_t)E_*E_, E_, pCQ + E_, nullptr, pQ, E_, NB, E_, D_, 0);

    build_kv<<<R1, 128>>>(pEMB, 0, nb1, edgef, ei1, et1, ts, NN, w_time, b_time, R1);
    launch_hgemm(pAh, pWh + 2*WSTRIDE, bk + E_, pK, R1);
    launch_hgemm(pAh, pWh + 3*WSTRIDE, bv + E_, pV, R1);

    attn_kernel<<<(NB + 3)/4, 128>>>(pQ, pK, pV, nb1, pCTX, pAM, NB);

    launch_gemm(pCTX, E_, Wo + (size_t)E_*E_, E_, bo + E_, pAM, pO, E_, NB, E_, E_, 0);
    {
        long tot = (long)NB * KPAD;
        build_cat<<<(int)((tot + 255)/256), 256>>>(pO, pSRC, NB);
    }
    launch_gemm(pA32, KPAD, W1 + (size_t)D_*DK_, DK_, b1 + D_, nullptr, pH, D_, NB, D_, DK_, 1);
    launch_gemm(pH, D_, W2 + (size_t)D_*D_, D_, b2 + D_, nullptr, out, D_, NB, D_, D_, 0);
}

// round 6
// speedup vs baseline: 1.0019x; 1.0019x over previous
#include <cuda_runtime.h>
#include <cuda_fp16.h>
#include <math.h>
#include <stdint.h>

// ---------------- problem constants ----------------
#define NB    1000      // B
#define NN    20        // neighbors per node
#define D_    172
#define DT_   100
#define E_    272       // D + DT
#define DK_   444       // D + DT + DE
#define KPAD  448       // padded K for the fp16 GEMM A buffer
#define HD    136       // head dim (E/2)

#define R1    (NB*NN)    // 20000 layer-1 queries
#define ROWS1 (R1*NN)    // 400000 layer-1 kv rows

// ---------------- scratch (device globals; no allocs allowed) ----------------
__device__ __align__(16) __half g_Ah [(size_t)ROWS1 * KPAD];  // fp16 gathered GEMM input
__device__ __align__(16) __half g_Wh [(size_t)4 * E_ * KPAD]; // fp16 weights [l*2+mat][272][448]
__device__ float g_A32 [(size_t)R1 * KPAD];   // fp32 input for MLP gemm
__device__ float g_K   [(size_t)ROWS1 * E_];
__device__ float g_V   [(size_t)ROWS1 * E_];
__device__ float g_SRC [(size_t)R1 * D_];
__device__ float g_Q   [(size_t)R1 * E_];
__device__ float g_CTX [(size_t)R1 * E_];
__device__ float g_O   [(size_t)R1 * E_];
__device__ float g_H   [(size_t)R1 * D_];
__device__ float g_EMB [(size_t)R1 * D_];
__device__ float g_CQ  [2 * E_];
__device__ int   g_AM  [R1];

// ============================================================================
// fp16 tensor-core GEMM via mma.sync (HMMA, valid at compute_103):
//   C[M, 272] = A[M, 448]fp16 @ W[272, 448]fp16^T + bias   (fp32 accum/output)
// CTA tile 128x96, BK=32 halfs, cp.async double buffer, ldmatrix fragments.
// Grid: (3, ceil(M/128)), 256 threads (8 warps as 4m x 2n, warp tile 32x48).
// ============================================================================
#define AST 40   // smem A row stride (halfs), padded
#define BST 40   // smem B row stride (halfs), padded

__device__ __forceinline__ void ldsm_x4(uint32_t* r, uint32_t addr) {
    asm volatile("ldmatrix.sync.aligned.m8n8.x4.shared.b16 {%0,%1,%2,%3}, [%4];"
                 : "=r"(r[0]), "=r"(r[1]), "=r"(r[2]), "=r"(r[3]) : "r"(addr));
}
__device__ __forceinline__ void mma16816(float* d, const uint32_t* a, uint32_t b0, uint32_t b1) {
    asm volatile("mma.sync.aligned.m16n8k16.row.col.f32.f16.f16.f32 "
                 "{%0,%1,%2,%3}, {%4,%5,%6,%7}, {%8,%9}, {%0,%1,%2,%3};"
                 : "+f"(d[0]), "+f"(d[1]), "+f"(d[2]), "+f"(d[3])
                 : "r"(a[0]), "r"(a[1]), "r"(a[2]), "r"(a[3]), "r"(b0), "r"(b1));
}
__device__ __forceinline__ void cp16(uint32_t dst, const void* src, int sz) {
    asm volatile("cp.async.cg.shared.global [%0], [%1], 16, %2;"
                 :: "r"(dst), "l"(src), "r"(sz));
}

__global__ __launch_bounds__(256)
void hgemm_mma(const __half* __restrict__ A, const __half* __restrict__ W,
               const float* __restrict__ bias, float* __restrict__ C, int M)
{
    __shared__ __half sA[2][128 * AST];
    __shared__ __half sB[2][96 * BST];

    const int tid  = threadIdx.x;
    const int lane = tid & 31, wid = tid >> 5;
    const int warp_m = wid & 3, warp_n = wid >> 2;
    const int m0 = blockIdx.y * 128;
    const int n0 = blockIdx.x * 96;

    float acc[2][6][4];
    #pragma unroll
    for (int i = 0; i < 2; i++)
        #pragma unroll
        for (int j = 0; j < 6; j++)
            #pragma unroll
            for (int q = 0; q < 4; q++) acc[i][j][q] = 0.f;

    // ---- async tile loaders (zero-fill OOB rows) ----
    auto loadA = [&](int s, int k0) {
        #pragma unroll
        for (int c = tid; c < 512; c += 256) {
            int row = c >> 2, seg = c & 3;
            int gm = m0 + row;
            uint32_t dst = (uint32_t)__cvta_generic_to_shared(&sA[s][row * AST + seg * 8]);
            cp16(dst, A + (size_t)gm * KPAD + k0 + seg * 8, gm < M ? 16 : 0);
        }
    };
    auto loadB = [&](int s, int k0) {
        #pragma unroll
        for (int c = tid; c < 384; c += 256) {
            int row = c >> 2, seg = c & 3;
            int gn = n0 + row;
            uint32_t dst = (uint32_t)__cvta_generic_to_shared(&sB[s][row * BST + seg * 8]);
            cp16(dst, W + (size_t)gn * KPAD + k0 + seg * 8, gn < E_ ? 16 : 0);
        }
    };

    auto computeStage = [&](int s) {
        #pragma unroll
        for (int kk = 0; kk < 2; ++kk) {
            uint32_t afr[2][4];
            #pragma unroll
            for (int i = 0; i < 2; ++i) {
                uint32_t addr = (uint32_t)__cvta_generic_to_shared(
                    &sA[s][(warp_m * 32 + i * 16 + (lane & 15)) * AST + kk * 16 + (lane >> 4) * 8]);
                ldsm_x4(afr[i], addr);
            }
            uint32_t bfr[3][4];
            #pragma unroll
            for (int j = 0; j < 3; ++j) {
                int nrow = warp_n * 48 + j * 16 + ((lane >> 4) << 3) + (lane & 7);
                int kcol = kk * 16 + ((lane >> 3) & 1) * 8;
                uint32_t addr = (uint32_t)__cvta_generic_to_shared(&sB[s][nrow * BST + kcol]);
                ldsm_x4(bfr[j], addr);
            }
            #pragma unroll
            for (int i = 0; i < 2; ++i)
                #pragma unroll
                for (int j = 0; j < 6; ++j)
                    mma16816(acc[i][j], afr[i], bfr[j >> 1][(j & 1) * 2], bfr[j >> 1][(j & 1) * 2 + 1]);
        }
    };

    loadA(0, 0); loadB(0, 0);
    asm volatile("cp.async.commit_group;" ::: "memory");

    for (int c = 0; c < 14; ++c) {
        if (c + 1 < 14) {
            loadA((c + 1) & 1, (c + 1) * 32);
            loadB((c + 1) & 1, (c + 1) * 32);
            asm volatile("cp.async.commit_group;" ::: "memory");
            asm volatile("cp.async.wait_group 1;" ::: "memory");
        } else {
            asm volatile("cp.async.wait_group 0;" ::: "memory");
        }
        __syncthreads();
        computeStage(c & 1);
        __syncthreads();
    }

    // ---- epilogue ----
    #pragma unroll
    for (int i = 0; i < 2; ++i) {
        int row = m0 + warp_m * 32 + i * 16 + (lane >> 2);
        #pragma unroll
        for (int j = 0; j < 6; ++j) {
            int col = n0 + warp_n * 48 + j * 8 + (lane & 3) * 2;
            if (col < E_) {
                float b0 = bias[col], b1 = bias[col + 1];
                if (row < M) {
                    C[(size_t)row * E_ + col]     = acc[i][j][0] + b0;
                    C[(size_t)row * E_ + col + 1] = acc[i][j][1] + b1;
                }
                if (row + 8 < M) {
                    C[(size_t)(row + 8) * E_ + col]     = acc[i][j][2] + b0;
                    C[(size_t)(row + 8) * E_ + col + 1] = acc[i][j][3] + b1;
                }
            }
        }
    }
}

// ---------------- weight conversion: Wk/Wv (2 layers) -> fp16 padded [4][272][448] ----------
__global__ void convert_w(const float* __restrict__ Wk, const float* __restrict__ Wv)
{
    const long total = 4L * E_ * KPAD;
    for (long i = (long)blockIdx.x * blockDim.x + threadIdx.x; i < total;
         i += (long)gridDim.x * blockDim.x) {
        int k = (int)(i % KPAD);
        long r = i / KPAD;
        int n = (int)(r % E_);
        int lm = (int)(r / E_);
        int mat = lm & 1, l = lm >> 1;
        const float* W = mat ? Wv : Wk;
        float v = (k < DK_) ? W[((size_t)l * E_ + n) * DK_ + k] : 0.f;
        g_Wh[i] = __float2half(v);
    }
}

// ---------------- constant part of q: c_q[l] = cos(b_time) @ Wq[l][:,172:].T + bq[l] ----
__global__ void cq_kernel(const float* __restrict__ Wq, const float* __restrict__ bq,
                          const float* __restrict__ b_time)
{
    int l = blockIdx.x;
    int n = threadIdx.x;
    if (n < E_) {
        float s = bq[l*E_ + n];
        const float* w = Wq + (size_t)l*E_*E_ + (size_t)n*E_ + D_;
        #pragma unroll 4
        for (int j = 0; j < DT_; j++) s += cosf(b_time[j]) * w[j];
        g_CQ[l*E_ + n] = s;
    }
}

// ---------------- generic row gather ----------------
__global__ void gather_rows(const float* __restrict__ src, const int* __restrict__ idx,
                            float* __restrict__ dst, int rows, int width)
{
    long total = (long)rows * width;
    for (long i = (long)blockIdx.x*blockDim.x + threadIdx.x; i < total;
         i += (long)gridDim.x * blockDim.x) {
        int r = (int)(i / width);
        int k = (int)(i % width);
        dst[i] = src[(size_t)idx[r]*width + k];
    }
}

// ---------------- build fp16 KV GEMM rows: [neigh(172) | cos(dt*w+b)(100) | edge(172) | 0] ----
__global__ void build_kv(const float* __restrict__ neigh_base, int gather_flag,
                         const int* __restrict__ neighbors,
                         const float* __restrict__ edge_features,
                         const int* __restrict__ edge_idxs,
                         const float* __restrict__ edge_times,
                         const float* __restrict__ timestamps, int ts_div,
                         const float* __restrict__ w_time, const float* __restrict__ b_time,
                         int rows)
{
    int m = blockIdx.x;
    if (m >= rows) return;
    __half2* out = (__half2*)(g_Ah + (size_t)m * KPAD);
    const float* nb = gather_flag ? (neigh_base + (size_t)neighbors[m]*D_)
                                  : (neigh_base + (size_t)m*D_);
    float dt = timestamps[m / ts_div] - edge_times[m];
    const float* ef = edge_features + (size_t)edge_idxs[m]*D_;
    for (int i = threadIdx.x; i < KPAD/2; i += blockDim.x) {
        int k = i * 2;
        float a, b;
        if (k < D_)            { a = nb[k]; b = nb[k+1]; }
        else if (k < E_)       { int j = k - D_;
                                 a = cosf(dt*w_time[j]   + b_time[j]);
                                 b = cosf(dt*w_time[j+1] + b_time[j+1]); }
        else if (k < DK_)      { a = ef[k - E_]; b = ef[k - E_ + 1]; }
        else                   { a = 0.f; b = 0.f; }
        out[i] = __floats2half2_rn(a, b);
    }
}

// ---------------- build fp32 MLP input rows: [o(272) | src(172) | 0pad] ----------------
__global__ void build_cat(const float* __restrict__ O, const float* __restrict__ S, int rows)
{
    long total = (long)rows * KPAD;
    for (long i = (long)blockIdx.x*blockDim.x + threadIdx.x; i < total;
         i += (long)gridDim.x * blockDim.x) {
        int r = (int)(i / KPAD);
        int k = (int)(i % KPAD);
        float v;
        if      (k < E_)  v = O[(size_t)r*E_ + k];
        else if (k < DK_) v = S[(size_t)r*D_ + (k - E_)];
        else              v = 0.f;
        g_A32[i] = v;
    }
}

// ---------------- fp32 tiled GEMM (small GEMMs): C = A @ W^T + bias ----------------
#define BM 128
#define BN 128
#define BK 16

__global__ __launch_bounds__(256)
void gemm_bias(const float* __restrict__ A, int lda,
               const float* __restrict__ W, int ldw,
               const float* __restrict__ bias,
               const int*   __restrict__ rowzero,
               float* __restrict__ C, int ldc,
               int M, int Ncols, int K, int relu)
{
    __shared__ float As[BK][BM + 4];
    __shared__ float Bs[BK][BN + 4];

    int tid = threadIdx.x;
    int tx = tid & 15, ty = tid >> 4;
    int m0 = blockIdx.y * BM, n0 = blockIdx.x * BN;

    float acc[8][8];
    #pragma unroll
    for (int i = 0; i < 8; i++)
        #pragma unroll
        for (int j = 0; j < 8; j++) acc[i][j] = 0.f;

    for (int k0 = 0; k0 < K; k0 += BK) {
        #pragma unroll
        for (int jj = 0; jj < 2; jj++) {
            int v  = tid + 256*jj;
            int m  = v >> 2;
            int k4 = v & 3;
            int gk = k0 + k4*4;

            float4 av = make_float4(0.f,0.f,0.f,0.f);
            int gm = m0 + m;
            if (gm < M && gk < K)
                av = *(const float4*)(A + (size_t)gm*lda + gk);
            As[k4*4+0][m]=av.x; As[k4*4+1][m]=av.y; As[k4*4+2][m]=av.z; As[k4*4+3][m]=av.w;

            float4 bv = make_float4(0.f,0.f,0.f,0.f);
            int gn = n0 + m;
            if (gn < Ncols && gk < K)
                bv = *(const float4*)(W + (size_t)gn*ldw + gk);
            Bs[k4*4+0][m]=bv.x; Bs[k4*4+1][m]=bv.y; Bs[k4*4+2][m]=bv.z; Bs[k4*4+3][m]=bv.w;
        }
        __syncthreads();

        #pragma unroll
        for (int kk = 0; kk < BK; kk++) {
            float ra[8], rb[8];
            #pragma unroll
            for (int i = 0; i < 8; i++) ra[i] = As[kk][ty + i*16];
            #pragma unroll
            for (int j = 0; j < 8; j++) rb[j] = Bs[kk][tx + j*16];
            #pragma unroll
            for (int i = 0; i < 8; i++)
                #pragma unroll
                for (int j = 0; j < 8; j++)
                    acc[i][j] += ra[i]*rb[j];
        }
        __syncthreads();
    }

    #pragma unroll
    for (int i = 0; i < 8; i++) {
        int gm = m0 + ty + i*16;
        if (gm >= M) continue;
        int rz = rowzero ? rowzero[gm] : 0;
        #pragma unroll
        for (int j = 0; j < 8; j++) {
            int gn = n0 + tx + j*16;
            if (gn >= Ncols) continue;
            float v = rz ? 0.f : (acc[i][j] + bias[gn]);
            if (relu) v = fmaxf(v, 0.f);
            C[(size_t)gm*ldc + gn] = v;
        }
    }
}

// ---------------- attention: warp per query row ----------------
__global__ void attn_kernel(const float* __restrict__ Q, const float* __restrict__ Kmat,
                            const float* __restrict__ Vmat, const int* __restrict__ nbrs,
                            float* __restrict__ CTX, int* __restrict__ AM, int R)
{
    __shared__ float qsh[4][E_];
    int warp = threadIdx.x >> 5, lane = threadIdx.x & 31;
    int row = blockIdx.x*4 + warp;
    if (row >= R) return;

    for (int d = lane; d < E_; d += 32) qsh[warp][d] = Q[(size_t)row*E_ + d];
    __syncwarp();

    const float scale = rsqrtf((float)HD);
    float a[2][NN];

    #pragma unroll
    for (int h = 0; h < 2; h++) {
        const float* qh = qsh[warp] + h*HD;
        for (int n = 0; n < NN; n++) {
            const float* kr = Kmat + ((size_t)row*NN + n)*E_ + h*HD;
            float s = 0.f;
            for (int d = lane; d < HD; d += 32) s += qh[d]*kr[d];
            #pragma unroll
            for (int o = 16; o; o >>= 1) s += __shfl_xor_sync(0xffffffffu, s, o);
            a[h][n] = s * scale;
        }
    }

    int allm = 1;
    #pragma unroll
    for (int n = 0; n < NN; n++) {
        int nb = nbrs[(size_t)row*NN + n];
        if (nb == 0) { a[0][n] = -1e9f; a[1][n] = -1e9f; }
        else allm = 0;
    }

    #pragma unroll
    for (int h = 0; h < 2; h++) {
        float mx = -3.4e38f;
        #pragma unroll
        for (int n = 0; n < NN; n++) mx = fmaxf(mx, a[h][n]);
        float ssum = 0.f;
        #pragma unroll
        for (int n = 0; n < NN; n++) { float e = expf(a[h][n] - mx); a[h][n] = e; ssum += e; }
        float inv = 1.f / ssum;
        #pragma unroll
        for (int n = 0; n < NN; n++) a[h][n] *= inv;
    }
    if (lane == 0) AM[row] = allm;

    for (int d = lane; d < E_; d += 32) {
        int h = d >= HD;
        float acc = 0.f;
        #pragma unroll
        for (int n = 0; n < NN; n++)
            acc += a[h][n] * Vmat[((size_t)row*NN + n)*E_ + d];
        CTX[(size_t)row*E_ + d] = acc;
    }
}

// ---------------- host side ----------------
static void launch_gemm(const float* A, int lda, const float* W, int ldw,
                        const float* bias, const int* rz,
                        float* C, int ldc, int M, int N, int K, int relu)
{
    dim3 grid((N + BN - 1)/BN, (M + BM - 1)/BM);
    gemm_bias<<<grid, 256>>>(A, lda, W, ldw, bias, rz, C, ldc, M, N, K, relu);
}

static void launch_hgemm(const __half* A, const __half* Wh, const float* bias, float* C, int M)
{
    dim3 grid(3, (M + 127)/128);
    hgemm_mma<<<grid, 256>>>(A, Wh, bias, C, M);
}

extern "C" void kernel_launch(void* const* d_in, const int* in_sizes, int n_in,
                              void* d_out, int out_size)
{
    const float* memory = (const float*)d_in[0];
    const float* edgef  = (const float*)d_in[1];
    const int*   srcn   = (const int*)  d_in[2];
    const float* ts     = (const float*)d_in[3];
    const int*   nb1    = (const int*)  d_in[4];
    const int*   ei1    = (const int*)  d_in[5];
    const float* et1    = (const float*)d_in[6];
    const int*   nb2    = (const int*)  d_in[7];
    const int*   ei2    = (const int*)  d_in[8];
    const float* et2    = (const float*)d_in[9];
    const float* w_time = (const float*)d_in[10];
    const float* b_time = (const float*)d_in[11];
    const float* Wq = (const float*)d_in[12];
    const float* bq = (const float*)d_in[13];
    const float* Wk = (const float*)d_in[14];
    const float* bk = (const float*)d_in[15];
    const float* Wv = (const float*)d_in[16];
    const float* bv = (const float*)d_in[17];
    const float* Wo = (const float*)d_in[18];
    const float* bo = (const float*)d_in[19];
    const float* W1 = (const float*)d_in[20];
    const float* b1 = (const float*)d_in[21];
    const float* W2 = (const float*)d_in[22];
    const float* b2 = (const float*)d_in[23];
    float* out = (float*)d_out;

    float *pA32, *pK, *pV, *pSRC, *pQ, *pCTX, *pO, *pH, *pEMB, *pCQ;
    __half *pAh, *pWh;
    int* pAM;
    cudaGetSymbolAddress((void**)&pAh,  g_Ah);
    cudaGetSymbolAddress((void**)&pWh,  g_Wh);
    cudaGetSymbolAddress((void**)&pA32, g_A32);
    cudaGetSymbolAddress((void**)&pK,   g_K);
    cudaGetSymbolAddress((void**)&pV,   g_V);
    cudaGetSymbolAddress((void**)&pSRC, g_SRC);
    cudaGetSymbolAddress((void**)&pQ,   g_Q);
    cudaGetSymbolAddress((void**)&pCTX, g_CTX);
    cudaGetSymbolAddress((void**)&pO,   g_O);
    cudaGetSymbolAddress((void**)&pH,   g_H);
    cudaGetSymbolAddress((void**)&pEMB, g_EMB);
    cudaGetSymbolAddress((void**)&pCQ,  g_CQ);
    cudaGetSymbolAddress((void**)&pAM,  g_AM);

    const size_t WSTRIDE = (size_t)E_ * KPAD;

    // weight fp16 conversion + constant query-time term
    convert_w<<<512, 256>>>(Wk, Wv);
    cq_kernel<<<2, E_>>>(Wq, bq, b_time);

    // ================= Layer 1 (l=0): 20000 queries x 20 neighbors =================
    {
        long tot = (long)R1 * D_;
        gather_rows<<<(int)((tot + 255)/256), 256>>>(memory, nb1, pSRC, R1, D_);
    }
    launch_gemm(pSRC, D_, Wq, E_, pCQ, nullptr, pQ, E_, R1, E_, D_, 0);

    build_kv<<<ROWS1, 128>>>(memory, 1, nb2, edgef, ei2, et2, ts, NN*NN, w_time, b_time, ROWS1);
    launch_hgemm(pAh, pWh + 0*WSTRIDE, bk, pK, ROWS1);
    launch_hgemm(pAh, pWh + 1*WSTRIDE, bv, pV, ROWS1);

    attn_kernel<<<(R1 + 3)/4, 128>>>(pQ, pK, pV, nb2, pCTX, pAM, R1);

    launch_gemm(pCTX, E_, Wo, E_, bo, pAM, pO, E_, R1, E_, E_, 0);
    {
        long tot = (long)R1 * KPAD;
        build_cat<<<(int)((tot + 255)/256), 256>>>(pO, pSRC, R1);
    }
    launch_gemm(pA32, KPAD, W1, DK_, b1, nullptr, pH, D_, R1, D_, DK_, 1);
    launch_gemm(pH, D_, W2, D_, b2, nullptr, pEMB, D_, R1, D_, D_, 0);

    // ================= Layer 2 (l=1): 1000 queries x 20 neighbors =================
    {
        long tot = (long)NB * D_;
        gather_rows<<<(int)((tot + 255)/256), 256>>>(memory, srcn, pSRC, NB, D_);
    }
    launch_gemm(pSRC, D_, Wq + (size_t)E_*E_, E_, pCQ + E_, nullptr, pQ, E_, NB, E_, D_, 0);

    build_kv<<<R1, 128>>>(pEMB, 0, nb1, edgef, ei1, et1, ts, NN, w_time, b_time, R1);
    launch_hgemm(pAh, pWh + 2*WSTRIDE, bk + E_, pK, R1);
    launch_hgemm(pAh, pWh + 3*WSTRIDE, bv + E_, pV, R1);

    attn_kernel<<<(NB + 3)/4, 128>>>(pQ, pK, pV, nb1, pCTX, pAM, NB);

    launch_gemm(pCTX, E_, Wo + (size_t)E_*E_, E_, bo + E_, pAM, pO, E_, NB, E_, E_, 0);
    {
        long tot = (long)NB * KPAD;
        build_cat<<<(int)((tot + 255)/256), 256>>>(pO, pSRC, NB);
    }
    launch_gemm(pA32, KPAD, W1 + (size_t)D_*DK_, DK_, b1 + D_, nullptr, pH, D_, NB, D_, DK_, 1);
    launch_gemm(pH, D_, W2 + (size_t)D_*D_, D_, b2 + D_, nullptr, out, D_, NB, D_, D_, 0);
}

// round 7
// speedup vs baseline: 1.6145x; 1.6115x over previous
#include <cuda_runtime.h>
#include <cuda_fp16.h>
#include <math.h>
#include <stdint.h>

// ---------------- problem constants ----------------
#define NB    1000      // B
#define NN    20        // neighbors per node
#define D_    172
#define DT_   100
#define E_    272       // D + DT
#define DK_   444       // D + DT + DE
#define KPAD  448       // padded K for the KV GEMM A buffer
#define HD    136       // head dim (E/2)
#define NKV   544       // fused K|V output width
#define QK    192       // padded K for Q gemm (172->192)
#define OK    288       // padded K for Wo gemm (272->288)
#define CST   288       // CTX row stride (fp16, zero-padded)

#define R1    (NB*NN)    // 20000 layer-1 queries
#define ROWS1 (R1*NN)    // 400000 layer-1 kv rows

// ---------------- scratch (device globals; zero-initialized, no allocs) ----------------
__device__ __align__(16) __half g_Ah  [(size_t)ROWS1 * KPAD]; // KV gemm input / MLP input (reused)
__device__ __align__(16) __half g_KVh [(size_t)ROWS1 * NKV];  // fused K|V output
__device__ __align__(16) __half g_Qh  [(size_t)R1 * E_];
__device__ __align__(16) __half g_CTXh[(size_t)R1 * CST];     // pad cols 272-287 stay 0
__device__ __align__(16) __half g_SRCh[(size_t)R1 * QK];      // pad cols 172-191 stay 0
__device__ __align__(16) __half g_Hh  [(size_t)R1 * QK];      // pad cols 172-191 stay 0
__device__ __align__(16) __half g_EMBh[(size_t)R1 * D_];
// fp16 weights (padded)
__device__ __align__(16) __half g_Wqh [(size_t)2 * E_ * QK];
__device__ __align__(16) __half g_WKVh[(size_t)2 * NKV * KPAD];
__device__ __align__(16) __half g_Woh [(size_t)2 * E_ * OK];
__device__ __align__(16) __half g_W1h [(size_t)2 * D_ * KPAD];
__device__ __align__(16) __half g_W2h [(size_t)2 * D_ * QK];
__device__ float g_bKV [2 * NKV];
__device__ float g_CQ  [2 * E_];
__device__ int   g_AM  [R1];

// ============================================================================
// fp16 tensor-core GEMM via mma.sync (HMMA):
//   C[M, N] = A[M, K]fp16 @ W[N, K]fp16^T + bias  (fp32 accum; fp16 or fp32 out)
// CTA tile 128x96, BK=32 halfs, cp.async double buffer, ldmatrix fragments.
// Grid: (ceil(N/96), ceil(M/128)), 256 threads (warps 4m x 2n, warp tile 32x48).
// ============================================================================
#define AST 40   // smem A row stride (halfs), padded
#define BST 40   // smem B row stride (halfs), padded

__device__ __forceinline__ void ldsm_x4(uint32_t* r, uint32_t addr) {
    asm volatile("ldmatrix.sync.aligned.m8n8.x4.shared.b16 {%0,%1,%2,%3}, [%4];"
                 : "=r"(r[0]), "=r"(r[1]), "=r"(r[2]), "=r"(r[3]) : "r"(addr));
}
__device__ __forceinline__ void mma16816(float* d, const uint32_t* a, uint32_t b0, uint32_t b1) {
    asm volatile("mma.sync.aligned.m16n8k16.row.col.f32.f16.f16.f32 "
                 "{%0,%1,%2,%3}, {%4,%5,%6,%7}, {%8,%9}, {%0,%1,%2,%3};"
                 : "+f"(d[0]), "+f"(d[1]), "+f"(d[2]), "+f"(d[3])
                 : "r"(a[0]), "r"(a[1]), "r"(a[2]), "r"(a[3]), "r"(b0), "r"(b1));
}
__device__ __forceinline__ void cp16(uint32_t dst, const void* src, int sz) {
    asm volatile("cp.async.cg.shared.global [%0], [%1], 16, %2;"
                 :: "r"(dst), "l"(src), "r"(sz));
}

template<int HALF_OUT>
__global__ __launch_bounds__(256)
void hgemm(const __half* __restrict__ A, int lda,
           const __half* __restrict__ W,
           const float* __restrict__ bias,
           const int* __restrict__ rowzero,
           void* __restrict__ Cout, int ldc,
           int M, int N, int K, int relu)
{
    __shared__ __half sA[2][128 * AST];
    __shared__ __half sB[2][96 * BST];

    const int tid  = threadIdx.x;
    const int lane = tid & 31, wid = tid >> 5;
    const int warp_m = wid & 3, warp_n = wid >> 2;
    const int m0 = blockIdx.y * 128;
    const int n0 = blockIdx.x * 96;
    const int nchunks = K >> 5;

    float acc[2][6][4];
    #pragma unroll
    for (int i = 0; i < 2; i++)
        #pragma unroll
        for (int j = 0; j < 6; j++)
            #pragma unroll
            for (int q = 0; q < 4; q++) acc[i][j][q] = 0.f;

    auto loadA = [&](int s, int k0) {
        #pragma unroll
        for (int c = tid; c < 512; c += 256) {
            int row = c >> 2, seg = c & 3;
            int gm = m0 + row;
            uint32_t dst = (uint32_t)__cvta_generic_to_shared(&sA[s][row * AST + seg * 8]);
            cp16(dst, A + (size_t)gm * lda + k0 + seg * 8, gm < M ? 16 : 0);
        }
    };
    auto loadB = [&](int s, int k0) {
        #pragma unroll
        for (int c = tid; c < 384; c += 256) {
            int row = c >> 2, seg = c & 3;
            int gn = n0 + row;
            uint32_t dst = (uint32_t)__cvta_generic_to_shared(&sB[s][row * BST + seg * 8]);
            cp16(dst, W + (size_t)gn * K + k0 + seg * 8, gn < N ? 16 : 0);
        }
    };

    auto computeStage = [&](int s) {
        #pragma unroll
        for (int kk = 0; kk < 2; ++kk) {
            uint32_t afr[2][4];
            #pragma unroll
            for (int i = 0; i < 2; ++i) {
                uint32_t addr = (uint32_t)__cvta_generic_to_shared(
                    &sA[s][(warp_m * 32 + i * 16 + (lane & 15)) * AST + kk * 16 + (lane >> 4) * 8]);
                ldsm_x4(afr[i], addr);
            }
            uint32_t bfr[3][4];
            #pragma unroll
            for (int j = 0; j < 3; ++j) {
                int nrow = warp_n * 48 + j * 16 + ((lane >> 4) << 3) + (lane & 7);
                int kcol = kk * 16 + ((lane >> 3) & 1) * 8;
                uint32_t addr = (uint32_t)__cvta_generic_to_shared(&sB[s][nrow * BST + kcol]);
                ldsm_x4(bfr[j], addr);
            }
            #pragma unroll
            for (int i = 0; i < 2; ++i)
                #pragma unroll
                for (int j = 0; j < 6; ++j)
                    mma16816(acc[i][j], afr[i], bfr[j >> 1][(j & 1) * 2], bfr[j >> 1][(j & 1) * 2 + 1]);
        }
    };

    loadA(0, 0); loadB(0, 0);
    asm volatile("cp.async.commit_group;" ::: "memory");

    for (int c = 0; c < nchunks; ++c) {
        if (c + 1 < nchunks) {
            loadA((c + 1) & 1, (c + 1) * 32);
            loadB((c + 1) & 1, (c + 1) * 32);
            asm volatile("cp.async.commit_group;" ::: "memory");
            asm volatile("cp.async.wait_group 1;" ::: "memory");
        } else {
            asm volatile("cp.async.wait_group 0;" ::: "memory");
        }
        __syncthreads();
        computeStage(c & 1);
        __syncthreads();
    }

    // ---- epilogue ----
    #pragma unroll
    for (int i = 0; i < 2; ++i) {
        int row = m0 + warp_m * 32 + i * 16 + (lane >> 2);
        #pragma unroll
        for (int j = 0; j < 6; ++j) {
            int col = n0 + warp_n * 48 + j * 8 + (lane & 3) * 2;
            if (col < N) {
                float b0 = bias[col], b1 = bias[col + 1];
                #pragma unroll
                for (int half_ = 0; half_ < 2; ++half_) {
                    int r = row + half_ * 8;
                    if (r < M) {
                        int rz = rowzero ? rowzero[r] : 0;
                        float v0 = rz ? 0.f : (acc[i][j][half_ * 2]     + b0);
                        float v1 = rz ? 0.f : (acc[i][j][half_ * 2 + 1] + b1);
                        if (relu) { v0 = fmaxf(v0, 0.f); v1 = fmaxf(v1, 0.f); }
                        if (HALF_OUT) {
                            *(__half2*)((__half*)Cout + (size_t)r * ldc + col) =
                                __floats2half2_rn(v0, v1);
                        } else {
                            float* cp = (float*)Cout + (size_t)r * ldc + col;
                            cp[0] = v0; cp[1] = v1;
                        }
                    }
                }
            }
        }
    }
}

// ---------------- generic weight convert+pad: dst[N][KP] <- src[N][Ksrc](first Kcopy) ----
__global__ void convert_pad(const float* __restrict__ src, __half* __restrict__ dst,
                            int N, int Ksrc, int Kcopy, int KP)
{
    long total = (long)N * KP;
    for (long i = (long)blockIdx.x * blockDim.x + threadIdx.x; i < total;
         i += (long)gridDim.x * blockDim.x) {
        int k = (int)(i % KP);
        int n = (int)(i / KP);
        dst[i] = __float2half(k < Kcopy ? src[(size_t)n * Ksrc + k] : 0.f);
    }
}

// ---------------- bias concat for fused KV ----------------
__global__ void concat_bkv(const float* __restrict__ bk, const float* __restrict__ bv)
{
    int l = blockIdx.x, n = threadIdx.x;
    if (n < NKV)
        g_bKV[l * NKV + n] = (n < E_) ? bk[l * E_ + n] : bv[l * E_ + n - E_];
}

// ---------------- constant part of q: c_q[l] = cos(b_time) @ Wq[l][:,172:].T + bq[l] ----
__global__ void cq_kernel(const float* __restrict__ Wq, const float* __restrict__ bq,
                          const float* __restrict__ b_time)
{
    int l = blockIdx.x;
    int n = threadIdx.x;
    if (n < E_) {
        float s = bq[l*E_ + n];
        const float* w = Wq + (size_t)l*E_*E_ + (size_t)n*E_ + D_;
        #pragma unroll 4
        for (int j = 0; j < DT_; j++) s += cosf(b_time[j]) * w[j];
        g_CQ[l*E_ + n] = s;
    }
}

// ---------------- gather memory rows -> fp16 SRC (stride QK, pads stay 0) ----------------
__global__ void gather_h(const float* __restrict__ src, const int* __restrict__ idx,
                         __half* __restrict__ dst, int rows)
{
    long total = (long)rows * D_;
    for (long i = (long)blockIdx.x*blockDim.x + threadIdx.x; i < total;
         i += (long)gridDim.x * blockDim.x) {
        int r = (int)(i / D_);
        int k = (int)(i % D_);
        dst[(size_t)r * QK + k] = __float2half(src[(size_t)idx[r]*D_ + k]);
    }
}

// ---------------- copy SRC into MLP-input cols [272, 444) of g_Ah ----------------
__global__ void copy_src(int rows)
{
    long total = (long)rows * D_;
    for (long i = (long)blockIdx.x*blockDim.x + threadIdx.x; i < total;
         i += (long)gridDim.x * blockDim.x) {
        int r = (int)(i / D_);
        int k = (int)(i % D_);
        g_Ah[(size_t)r * KPAD + E_ + k] = g_SRCh[(size_t)r * QK + k];
    }
}

// ---------------- build fp16 KV GEMM rows (warp per row):
// [neigh(172) | cos(dt*w+b)(100) | edge(172) | 0pad(4)]
__global__ void build_kv(const float* __restrict__ memf,      // layer1: gather via neighbors
                         const __half* __restrict__ memh,     // layer2: row m direct (stride D_)
                         const int* __restrict__ neighbors,
                         const float* __restrict__ edge_features,
                         const int* __restrict__ edge_idxs,
                         const float* __restrict__ edge_times,
                         const float* __restrict__ timestamps, int ts_div,
                         const float* __restrict__ w_time, const float* __restrict__ b_time,
                         int rows)
{
    int warp = threadIdx.x >> 5, lane = threadIdx.x & 31;
    int m = blockIdx.x * 4 + warp;
    if (m >= rows) return;

    __half2* out = (__half2*)(g_Ah + (size_t)m * KPAD);
    const float*  nbf = memf ? memf + (size_t)neighbors[m] * D_ : nullptr;
    const __half* nbh = memf ? nullptr : memh + (size_t)m * D_;
    float dt = timestamps[m / ts_div] - edge_times[m];
    const float* ef = edge_features + (size_t)edge_idxs[m] * D_;

    #pragma unroll
    for (int i = lane; i < KPAD/2; i += 32) {
        int k = i * 2;
        float a, b;
        if (k < D_) {
            if (nbf) { a = nbf[k]; b = nbf[k+1]; }
            else     { __half2 h = *(const __half2*)(nbh + k); float2 f = __half22float2(h); a = f.x; b = f.y; }
        } else if (k < E_) {
            int j = k - D_;
            a = cosf(dt*w_time[j]   + b_time[j]);
            b = cosf(dt*w_time[j+1] + b_time[j+1]);
        } else if (k < DK_) {
            a = ef[k - E_]; b = ef[k - E_ + 1];
        } else { a = 0.f; b = 0.f; }
        out[i] = __floats2half2_rn(a, b);
    }
}

// ---------------- attention: warp per query row, fp16 in/out ----------------
__global__ void attn_kernel(const __half* __restrict__ Q, const __half* __restrict__ KV,
                            const int* __restrict__ nbrs,
                            __half* __restrict__ CTX, int* __restrict__ AM, int R)
{
    __shared__ float qsh[4][E_];
    int warp = threadIdx.x >> 5, lane = threadIdx.x & 31;
    int row = blockIdx.x*4 + warp;
    if (row >= R) return;

    for (int d = lane; d < E_; d += 32)
        qsh[warp][d] = __half2float(Q[(size_t)row*E_ + d]);
    __syncwarp();

    const float scale = rsqrtf((float)HD);
    float a[2][NN];

    #pragma unroll
    for (int h = 0; h < 2; h++) {
        const float* qh = qsh[warp] + h*HD;
        for (int n = 0; n < NN; n++) {
            const __half2* k2 = (const __half2*)(KV + ((size_t)row*NN + n)*NKV + h*HD);
            float s = 0.f;
            for (int i = lane; i < HD/2; i += 32) {
                float2 kf = __half22float2(k2[i]);
                s += qh[2*i]*kf.x + qh[2*i+1]*kf.y;
            }
            #pragma unroll
            for (int o = 16; o; o >>= 1) s += __shfl_xor_sync(0xffffffffu, s, o);
            a[h][n] = s * scale;
        }
    }

    int allm = 1;
    #pragma unroll
    for (int n = 0; n < NN; n++) {
        int nb = nbrs[(size_t)row*NN + n];
        if (nb == 0) { a[0][n] = -1e9f; a[1][n] = -1e9f; }
        else allm = 0;
    }

    #pragma unroll
    for (int h = 0; h < 2; h++) {
        float mx = -3.4e38f;
        #pragma unroll
        for (int n = 0; n < NN; n++) mx = fmaxf(mx, a[h][n]);
        float ssum = 0.f;
        #pragma unroll
        for (int n = 0; n < NN; n++) { float e = expf(a[h][n] - mx); a[h][n] = e; ssum += e; }
        float inv = 1.f / ssum;
        #pragma unroll
        for (int n = 0; n < NN; n++) a[h][n] *= inv;
    }
    if (lane == 0) AM[row] = allm;

    for (int i = lane; i < E_/2; i += 32) {
        int h = (2*i) >= HD;
        float ax = 0.f, ay = 0.f;
        #pragma unroll
        for (int n = 0; n < NN; n++) {
            const __half2* v2 = (const __half2*)(KV + ((size_t)row*NN + n)*NKV + E_);
            float2 vf = __half22float2(v2[i]);
            ax += a[h][n] * vf.x;
            ay += a[h][n] * vf.y;
        }
        *(__half2*)(CTX + (size_t)row*CST + 2*i) = __floats2half2_rn(ax, ay);
    }
}

// ---------------- host helpers ----------------
static void launch_hgemm_h(const __half* A, int lda, const __half* W, const float* bias,
                           const int* rz, __half* C, int ldc, int M, int N, int K, int relu)
{
    dim3 grid((N + 95)/96, (M + 127)/128);
    hgemm<1><<<grid, 256>>>(A, lda, W, bias, rz, (void*)C, ldc, M, N, K, relu);
}
static void launch_hgemm_f(const __half* A, int lda, const __half* W, const float* bias,
                           const int* rz, float* C, int ldc, int M, int N, int K, int relu)
{
    dim3 grid((N + 95)/96, (M + 127)/128);
    hgemm<0><<<grid, 256>>>(A, lda, W, bias, rz, (void*)C, ldc, M, N, K, relu);
}

extern "C" void kernel_launch(void* const* d_in, const int* in_sizes, int n_in,
                              void* d_out, int out_size)
{
    const float* memory = (const float*)d_in[0];
    const float* edgef  = (const float*)d_in[1];
    const int*   srcn   = (const int*)  d_in[2];
    const float* ts     = (const float*)d_in[3];
    const int*   nb1    = (const int*)  d_in[4];
    const int*   ei1    = (const int*)  d_in[5];
    const float* et1    = (const float*)d_in[6];
    const int*   nb2    = (const int*)  d_in[7];
    const int*   ei2    = (const int*)  d_in[8];
    const float* et2    = (const float*)d_in[9];
    const float* w_time = (const float*)d_in[10];
    const float* b_time = (const float*)d_in[11];
    const float* Wq = (const float*)d_in[12];
    const float* bq = (const float*)d_in[13];
    const float* Wk = (const float*)d_in[14];
    const float* bk = (const float*)d_in[15];
    const float* Wv = (const float*)d_in[16];
    const float* bv = (const float*)d_in[17];
    const float* Wo = (const float*)d_in[18];
    const float* bo = (const float*)d_in[19];
    const float* W1 = (const float*)d_in[20];
    const float* b1 = (const float*)d_in[21];
    const float* W2 = (const float*)d_in[22];
    const float* b2 = (const float*)d_in[23];
    float* out = (float*)d_out;

    __half *pAh, *pKVh, *pQh, *pCTXh, *pSRCh, *pHh, *pEMBh;
    __half *pWqh, *pWKVh, *pWoh, *pW1h, *pW2h;
    float *pbKV, *pCQ;
    int* pAM;
    cudaGetSymbolAddress((void**)&pAh,   g_Ah);
    cudaGetSymbolAddress((void**)&pKVh,  g_KVh);
    cudaGetSymbolAddress((void**)&pQh,   g_Qh);
    cudaGetSymbolAddress((void**)&pCTXh, g_CTXh);
    cudaGetSymbolAddress((void**)&pSRCh, g_SRCh);
    cudaGetSymbolAddress((void**)&pHh,   g_Hh);
    cudaGetSymbolAddress((void**)&pEMBh, g_EMBh);
    cudaGetSymbolAddress((void**)&pWqh,  g_Wqh);
    cudaGetSymbolAddress((void**)&pWKVh, g_WKVh);
    cudaGetSymbolAddress((void**)&pWoh,  g_Woh);
    cudaGetSymbolAddress((void**)&pW1h,  g_W1h);
    cudaGetSymbolAddress((void**)&pW2h,  g_W2h);
    cudaGetSymbolAddress((void**)&pbKV,  g_bKV);
    cudaGetSymbolAddress((void**)&pCQ,   g_CQ);
    cudaGetSymbolAddress((void**)&pAM,   g_AM);

    // ---- weight conversion (tiny) ----
    for (int l = 0; l < 2; ++l) {
        convert_pad<<<64, 256>>>(Wq + (size_t)l*E_*E_,  pWqh  + (size_t)l*E_*QK,            E_, E_,  D_,  QK);
        convert_pad<<<128,256>>>(Wk + (size_t)l*E_*DK_, pWKVh + (size_t)l*NKV*KPAD,          E_, DK_, DK_, KPAD);
        convert_pad<<<128,256>>>(Wv + (size_t)l*E_*DK_, pWKVh + (size_t)l*NKV*KPAD + (size_t)E_*KPAD, E_, DK_, DK_, KPAD);
        convert_pad<<<64, 256>>>(Wo + (size_t)l*E_*E_,  pWoh  + (size_t)l*E_*OK,            E_, E_,  E_,  OK);
        convert_pad<<<128,256>>>(W1 + (size_t)l*D_*DK_, pW1h  + (size_t)l*D_*KPAD,          D_, DK_, DK_, KPAD);
        convert_pad<<<64, 256>>>(W2 + (size_t)l*D_*D_,  pW2h  + (size_t)l*D_*QK,            D_, D_,  D_,  QK);
    }
    concat_bkv<<<2, NKV>>>(bk, bv);
    cq_kernel<<<2, E_>>>(Wq, bq, b_time);

    const size_t WQs = (size_t)E_*QK, WKVs = (size_t)NKV*KPAD, WOs = (size_t)E_*OK,
                 W1s = (size_t)D_*KPAD, W2s = (size_t)D_*QK;

    // ================= Layer 1 (l=0): 20000 queries x 20 neighbors =================
    gather_h<<<(R1*D_ + 255)/256, 256>>>(memory, nb1, pSRCh, R1);
    launch_hgemm_h(pSRCh, QK, pWqh, pCQ, nullptr, pQh, E_, R1, E_, QK, 0);

    build_kv<<<(ROWS1 + 3)/4, 128>>>(memory, nullptr, nb2, edgef, ei2, et2, ts, NN*NN,
                                     w_time, b_time, ROWS1);
    launch_hgemm_h(pAh, KPAD, pWKVh, pbKV, nullptr, pKVh, NKV, ROWS1, NKV, KPAD, 0);

    attn_kernel<<<(R1 + 3)/4, 128>>>(pQh, pKVh, nb2, pCTXh, pAM, R1);

    launch_hgemm_h(pCTXh, CST, pWoh, bo, pAM, pAh, KPAD, R1, E_, OK, 0);  // O -> g_Ah cols 0-271
    copy_src<<<(R1*D_ + 255)/256, 256>>>(R1);                              // SRC -> cols 272-443
    launch_hgemm_h(pAh, KPAD, pW1h, b1, nullptr, pHh, QK, R1, D_, KPAD, 1);
    launch_hgemm_h(pHh, QK, pW2h, b2, nullptr, pEMBh, D_, R1, D_, QK, 0);

    // ================= Layer 2 (l=1): 1000 queries x 20 neighbors =================
    gather_h<<<(NB*D_ + 255)/256, 256>>>(memory, srcn, pSRCh, NB);
    launch_hgemm_h(pSRCh, QK, pWqh + WQs, pCQ + E_, nullptr, pQh, E_, NB, E_, QK, 0);

    build_kv<<<(R1 + 3)/4, 128>>>(nullptr, pEMBh, nb1, edgef, ei1, et1, ts, NN,
                                  w_time, b_time, R1);
    launch_hgemm_h(pAh, KPAD, pWKVh + WKVs, pbKV + NKV, nullptr, pKVh, NKV, R1, NKV, KPAD, 0);

    attn_kernel<<<(NB + 3)/4, 128>>>(pQh, pKVh, nb1, pCTXh, pAM, NB);

    launch_hgemm_h(pCTXh, CST, pWoh + WOs, bo + E_, pAM, pAh, KPAD, NB, E_, OK, 0);
    copy_src<<<(NB*D_ + 255)/256, 256>>>(NB);
    launch_hgemm_h(pAh, KPAD, pW1h + W1s, b1 + D_, nullptr, pHh, QK, NB, D_, KPAD, 1);
    launch_hgemm_f(pHh, QK, pW2h + W2s, b2 + D_, nullptr, out, D_, NB, D_, QK, 0);
}